// round 17
// baseline (speedup 1.0000x reference)
#include <cuda_runtime.h>
#include <cuda_fp16.h>
#include <math.h>
#include <stdint.h>

#define E_DIM 1024
#define H_DIM 16
#define D_DIM 64
#define S_LEN 1024
#define N_B   4
#define L_NUM 4
#define FF_DIM 4096
#define V_DIM 32000
#define M_TOK (N_B * S_LEN)   // 4096 token rows
#define QKV_STR (3 * E_DIM)   // 3072

// ---------------------------------------------------------------------------
// Transposed-weight half buffer layout (element offsets)
// ---------------------------------------------------------------------------
#define QKV_LSTR   (3 * E_DIM * E_DIM)
#define OFF_WO     (L_NUM * QKV_LSTR)
#define WO_LSTR    (E_DIM * E_DIM)
#define OFF_W1     (OFF_WO + L_NUM * WO_LSTR)
#define W1_LSTR    (E_DIM * FF_DIM)
#define OFF_W2     (OFF_W1 + L_NUM * W1_LSTR)
#define W2_LSTR    (FF_DIM * E_DIM)
#define OFF_WOUT   (OFF_W2 + L_NUM * W2_LSTR)
#define WH_TOTAL   (OFF_WOUT + (size_t)V_DIM * E_DIM)

// ---------------------------------------------------------------------------
// Scratch (device globals; no allocations allowed)
// ---------------------------------------------------------------------------
__device__ float  g_act  [M_TOK * E_DIM];
__device__ __half g_act_h[M_TOK * E_DIM];
__device__ __half g_qkv_h[M_TOK * QKV_STR];
__device__ __half g_attn_h[M_TOK * E_DIM];
__device__ float  g_tmp  [M_TOK * E_DIM];
__device__ float  g_h    [M_TOK * E_DIM];
__device__ __half g_h_h  [M_TOK * E_DIM];
__device__ __half g_ff_h [M_TOK * FF_DIM];
__device__ float  g_bqkv [L_NUM * QKV_STR];
__device__ __half g_wh   [WH_TOTAL];

__device__ __forceinline__ uint32_t smem_u32(const void* p) {
    uint32_t a;
    asm("{ .reg .u64 t; cvta.to.shared.u64 t, %1; cvt.u32.u64 %0, t; }"
        : "=r"(a) : "l"(p));
    return a;
}

__device__ __forceinline__ void ldsm_x4(uint32_t* r, uint32_t addr) {
    asm volatile("ldmatrix.sync.aligned.m8n8.x4.shared.b16 {%0,%1,%2,%3}, [%4];"
                 : "=r"(r[0]), "=r"(r[1]), "=r"(r[2]), "=r"(r[3]) : "r"(addr));
}
__device__ __forceinline__ void ldsm_x4t(uint32_t* r, uint32_t addr) {
    asm volatile("ldmatrix.sync.aligned.m8n8.x4.trans.shared.b16 {%0,%1,%2,%3}, [%4];"
                 : "=r"(r[0]), "=r"(r[1]), "=r"(r[2]), "=r"(r[3]) : "r"(addr));
}
__device__ __forceinline__ void mma16816(float* c, const uint32_t* a,
                                         uint32_t b0, uint32_t b1) {
    asm volatile(
        "mma.sync.aligned.m16n8k16.row.col.f32.f16.f16.f32 "
        "{%0,%1,%2,%3}, {%4,%5,%6,%7}, {%8,%9}, {%0,%1,%2,%3};\n"
        : "+f"(c[0]), "+f"(c[1]), "+f"(c[2]), "+f"(c[3])
        : "r"(a[0]), "r"(a[1]), "r"(a[2]), "r"(a[3]), "r"(b0), "r"(b1));
}
__device__ __forceinline__ uint32_t f22h(float a, float b) {
    __half2 h = __floats2half2_rn(a, b);
    return *(uint32_t*)&h;
}

// ---------------------------------------------------------------------------
// Embedding + sinusoidal positional encoding (writes f32 + half copies)
// ---------------------------------------------------------------------------
__global__ void embed_kernel(const int* __restrict__ x,
                             const float* __restrict__ emb,
                             float* __restrict__ out,
                             __half* __restrict__ outh)
{
    int row = blockIdx.x;
    int s   = row & (S_LEN - 1);
    int tok = x[row];
    const float* erow = emb + (size_t)tok * E_DIM;
    float* orow = out + (size_t)row * E_DIM;
    __half* ohrow = outh + (size_t)row * E_DIM;

    int e0 = threadIdx.x * 4;
    #pragma unroll
    for (int j = 0; j < 4; j++) {
        int e = e0 + j;
        int even = e & ~1;
        float expo = (float)even / (float)E_DIM;
        float denom = powf(10000.0f, expo);
        float ang = (float)s / denom;
        float pe = (e & 1) ? cosf(ang) : sinf(ang);
        float v = erow[e] + pe;
        orow[e] = v;
        ohrow[e] = __float2half_rn(v);
    }
}

// ---------------------------------------------------------------------------
// Batched transpose+half, 64x64 tiles, swizzled SMEM, float4 loads.
// ---------------------------------------------------------------------------
__global__ __launch_bounds__(256)
void transpose_half_b4(const float* __restrict__ W, __half* __restrict__ dst,
                       int Kd, int Nd, size_t src_stride, size_t dst_stride)
{
    __shared__ float tile[64][64];
    const float* Wz = W + (size_t)blockIdx.z * src_stride;
    __half* Dz = dst + (size_t)blockIdx.z * dst_stride;
    int n0 = blockIdx.x * 64, k0 = blockIdx.y * 64;
    int tx = threadIdx.x, ty = threadIdx.y;   // 16 x 16

    #pragma unroll
    for (int i = 0; i < 4; i++) {
        int r = ty + 16 * i;
        float4 v = *(const float4*)(Wz + (size_t)(k0 + r) * Nd + n0 + 4 * tx);
        tile[r][(4 * tx     + r) & 63] = v.x;
        tile[r][(4 * tx + 1 + r) & 63] = v.y;
        tile[r][(4 * tx + 2 + r) & 63] = v.z;
        tile[r][(4 * tx + 3 + r) & 63] = v.w;
    }
    __syncthreads();
    #pragma unroll
    for (int i = 0; i < 4; i++) {
        int nr = ty + 16 * i;
        float a0 = tile[4 * tx    ][(nr + 4 * tx)     & 63];
        float a1 = tile[4 * tx + 1][(nr + 4 * tx + 1) & 63];
        float a2 = tile[4 * tx + 2][(nr + 4 * tx + 2) & 63];
        float a3 = tile[4 * tx + 3][(nr + 4 * tx + 3) & 63];
        uint2 u;
        u.x = f22h(a0, a1);
        u.y = f22h(a2, a3);
        *(uint2*)(Dz + (size_t)(n0 + nr) * Kd + k0 + 4 * tx) = u;
    }
}

__global__ void pack_qkv_bias(const float* __restrict__ bq,
                              const float* __restrict__ bk,
                              const float* __restrict__ bv,
                              float* __restrict__ out)
{
    int i = blockIdx.x * 256 + threadIdx.x;
    int layer = i / QKV_STR, c = i % QKV_STR;
    float v;
    if (c < E_DIM)           v = bq[layer * E_DIM + c];
    else if (c < 2 * E_DIM)  v = bk[layer * E_DIM + c - E_DIM];
    else                     v = bv[layer * E_DIM + c - 2 * E_DIM];
    out[i] = v;
}

// ---------------------------------------------------------------------------
// FP16 GEMM: CTA 128x128, warp 64x32, BK=32, ROWB=112, 3-stage cp.async,
// 2 CTAs/SM. Grid: x = M tiles (fastest).
// ---------------------------------------------------------------------------
#define GBM 128
#define GBN 128
#define GBK 32
#define ROWB 112
#define OP_ST (128 * ROWB)
#define STG   (2 * OP_ST)
#define NST   3
#define GEMM_SMEM (NST * STG)

template<int RELU, int WF, int WH, int ADDR>
__global__ __launch_bounds__(256, 2)
void hgemm5(const __half* __restrict__ A, const __half* __restrict__ Bt,
            const float* __restrict__ bias, const float* __restrict__ Rf,
            float* __restrict__ Cf, __half* __restrict__ Ch,
            int Nd, int Kd)
{
    extern __shared__ char smem[];
    const uint32_t sbase = smem_u32(smem);

    const int tid  = threadIdx.x;
    const int lane = tid & 31;
    const int wid  = tid >> 5;
    const int gid  = lane >> 2;
    const int tig  = lane & 3;

    const int m0 = blockIdx.x * GBM;
    const int n0 = blockIdx.y * GBN;
    const int wm = (wid >> 2) * 64;
    const int wn = (wid & 3) * 32;

    const int arow   = wm + (lane & 15);
    const int akoh   = (lane & 16) ? 8 : 0;
    const int brow16 = wn + (lane & 7) + ((lane & 16) ? 8 : 0);
    const int bkoh   = (lane & 8) ? 8 : 0;

    const int s_row = tid >> 2;
    const int s_q   = tid & 3;

    float acc[4][4][4];
    #pragma unroll
    for (int i = 0; i < 4; i++)
        #pragma unroll
        for (int j = 0; j < 4; j++)
            #pragma unroll
            for (int r = 0; r < 4; r++) acc[i][j][r] = 0.0f;

    const int nK = Kd / GBK;

    auto issue_stage = [&](int t, int buf) {
        const uint32_t base = sbase + buf * STG;
        const __half* Ag = A + (size_t)m0 * Kd + t * GBK;
        const __half* Bg = Bt + (size_t)n0 * Kd + t * GBK;
        #pragma unroll
        for (int p = 0; p < 2; p++) {
            int r = s_row + p * 64;
            uint32_t da = base + r * ROWB + s_q * 16;
            const __half* sa = Ag + (size_t)r * Kd + s_q * 8;
            asm volatile("cp.async.cg.shared.global [%0], [%1], 16;\n"
                         :: "r"(da), "l"(sa));
            uint32_t db = base + OP_ST + r * ROWB + s_q * 16;
            const __half* sb = Bg + (size_t)r * Kd + s_q * 8;
            asm volatile("cp.async.cg.shared.global [%0], [%1], 16;\n"
                         :: "r"(db), "l"(sb));
        }
        asm volatile("cp.async.commit_group;\n");
    };

    issue_stage(0, 0);
    if (nK > 1) issue_stage(1, 1);

    int buf = 0;
    for (int t = 0; t < nK; t++) {
        if (t + 1 < nK) asm volatile("cp.async.wait_group 1;\n");
        else            asm volatile("cp.async.wait_group 0;\n");
        __syncthreads();

        if (t + 2 < nK) {
            int nb = buf + 2; if (nb >= NST) nb -= NST;
            issue_stage(t + 2, nb);
        }

        const uint32_t sA = sbase + buf * STG;
        const uint32_t sB = sA + OP_ST;
        #pragma unroll
        for (int ko = 0; ko < GBK; ko += 16) {
            uint32_t af[4][4], bf[4][2];
            #pragma unroll
            for (int mt = 0; mt < 4; mt++)
                ldsm_x4(af[mt], sA + (arow + mt * 16) * ROWB + (ko + akoh) * 2);
            #pragma unroll
            for (int g = 0; g < 2; g++) {
                uint32_t r[4];
                ldsm_x4(r, sB + (brow16 + g * 16) * ROWB + (ko + bkoh) * 2);
                bf[2 * g][0] = r[0]; bf[2 * g][1] = r[1];
                bf[2 * g + 1][0] = r[2]; bf[2 * g + 1][1] = r[3];
            }
            #pragma unroll
            for (int mt = 0; mt < 4; mt++)
                #pragma unroll
                for (int nt = 0; nt < 4; nt++)
                    mma16816(acc[mt][nt], af[mt], bf[nt][0], bf[nt][1]);
        }
        if (++buf >= NST) buf = 0;
    }

    #pragma unroll
    for (int nt = 0; nt < 4; nt++) {
        int col = n0 + wn + nt * 8 + 2 * tig;
        float b0 = bias[col];
        float b1 = bias[col + 1];
        #pragma unroll
        for (int mt = 0; mt < 4; mt++) {
            int row = m0 + wm + mt * 16 + gid;
            float v00 = acc[mt][nt][0] + b0;
            float v01 = acc[mt][nt][1] + b1;
            float v10 = acc[mt][nt][2] + b0;
            float v11 = acc[mt][nt][3] + b1;
            if (ADDR) {
                float2 r0 = *(const float2*)(Rf + (size_t)row * Nd + col);
                float2 r1 = *(const float2*)(Rf + (size_t)(row + 8) * Nd + col);
                v00 += r0.x; v01 += r0.y;
                v10 += r1.x; v11 += r1.y;
            }
            if (RELU) {
                v00 = fmaxf(v00, 0.0f); v01 = fmaxf(v01, 0.0f);
                v10 = fmaxf(v10, 0.0f); v11 = fmaxf(v11, 0.0f);
            }
            if (WF) {
                float2 f0 = {v00, v01}, f1 = {v10, v11};
                *(float2*)(Cf + (size_t)row * Nd + col)       = f0;
                *(float2*)(Cf + (size_t)(row + 8) * Nd + col) = f1;
            }
            if (WH) {
                __half2 h0 = __floats2half2_rn(v00, v01);
                __half2 h1 = __floats2half2_rn(v10, v11);
                *(__half2*)(Ch + (size_t)row * Nd + col)       = h0;
                *(__half2*)(Ch + (size_t)(row + 8) * Nd + col) = h1;
            }
        }
    }
}

// ---------------------------------------------------------------------------
// FP16 flash attention, 64-row q tiles, 64-row k tiles, 128 threads (4 warps),
// multiple CTAs/SM. Warp w owns q rows [16w, 16w+16) of the 64-row tile.
// ---------------------------------------------------------------------------
#define AROWB 144
#define ATOP  (64 * AROWB)            // 9216 per 64-row operand tile
#define ATTN_SMEM (5 * ATOP)          // Q + 2K + 2V = 46080

__global__ __launch_bounds__(128)
void flash_attn_h(const __half* __restrict__ QKV, __half* __restrict__ O)
{
    extern __shared__ char smem[];
    const uint32_t sbase = smem_u32(smem);
    const uint32_t sQ = sbase;

    const int tid  = threadIdx.x;
    const int lane = tid & 31;
    const int wid  = tid >> 5;       // 0..3
    const int gid  = lane >> 2;
    const int tig  = lane & 3;

    const int qt = gridDim.x - 1 - blockIdx.x;   // big tiles first
    const int h  = blockIdx.y;
    const int n  = blockIdx.z;
    const size_t rowbase = (size_t)n * S_LEN;
    const int hq = h * D_DIM;
    const int hk = E_DIM + h * D_DIM;
    const int hv = 2 * E_DIM + h * D_DIM;
    const size_t bout = rowbase * E_DIM + h * D_DIM;
    const float scale = 1.0f / 32.0f;
    const int wrow = wid * 16;
    const int rbase = wrow + gid;     // local q row (0..63)

    const int s_r = tid >> 1;         // 0..63
    const int s_q = tid & 1;          // chunk parity

    // ---- stage Q (64-row tile qt) ----
    {
        const __half* src = QKV + (rowbase + qt * 64 + s_r) * QKV_STR + hq;
        #pragma unroll
        for (int j = 0; j < 4; j++) {
            int q = s_q + 2 * j;
            asm volatile("cp.async.cg.shared.global [%0], [%1], 16;\n"
                         :: "r"(sQ + s_r * AROWB + q * 16), "l"(src + q * 8));
        }
    }

    auto stage_kv = [&](int kt, int b) {
        const uint32_t sK = sbase + ATOP + b * ATOP;
        const uint32_t sV = sbase + 3 * ATOP + b * ATOP;
        const __half* srck = QKV + (rowbase + kt * 64 + s_r) * QKV_STR + hk;
        const __half* srcv = QKV + (rowbase + kt * 64 + s_r) * QKV_STR + hv;
        #pragma unroll
        for (int j = 0; j < 4; j++) {
            int q = s_q + 2 * j;
            asm volatile("cp.async.cg.shared.global [%0], [%1], 16;\n"
                         :: "r"(sK + s_r * AROWB + q * 16), "l"(srck + q * 8));
            asm volatile("cp.async.cg.shared.global [%0], [%1], 16;\n"
                         :: "r"(sV + s_r * AROWB + q * 16), "l"(srcv + q * 8));
        }
    };

    stage_kv(0, 0);
    asm volatile("cp.async.commit_group;\n");

    float accO[8][4];
    #pragma unroll
    for (int i = 0; i < 8; i++)
        #pragma unroll
        for (int j = 0; j < 4; j++) accO[i][j] = 0.0f;
    float m0 = -1e30f, m1 = -1e30f, l0 = 0.0f, l1 = 0.0f;

    int buf = 0;
    for (int kt = 0; kt <= qt; kt++) {
        asm volatile("cp.async.wait_group 0;\n");
        __syncthreads();
        if (kt < qt) {
            stage_kv(kt + 1, buf ^ 1);
            asm volatile("cp.async.commit_group;\n");
        }
        const uint32_t sK = sbase + ATOP + buf * ATOP;
        const uint32_t sV = sbase + 3 * ATOP + buf * ATOP;

        // ---- S = Q K^T (16 q rows x 64 keys per warp) ----
        float accS[8][4];
        #pragma unroll
        for (int i = 0; i < 8; i++)
            #pragma unroll
            for (int j = 0; j < 4; j++) accS[i][j] = 0.0f;

        #pragma unroll
        for (int ko = 0; ko < 64; ko += 16) {
            uint32_t af[4];
            ldsm_x4(af, sQ + (wrow + (lane & 15)) * AROWB
                        + (ko + ((lane & 16) ? 8 : 0)) * 2);
            #pragma unroll
            for (int g = 0; g < 4; g++) {
                uint32_t kr[4];
                ldsm_x4(kr, sK + (g * 16 + (lane & 7) + ((lane & 16) ? 8 : 0)) * AROWB
                            + (ko + ((lane & 8) ? 8 : 0)) * 2);
                mma16816(accS[2 * g],     af, kr[0], kr[1]);
                mma16816(accS[2 * g + 1], af, kr[2], kr[3]);
            }
        }

        // ---- scale ----
        #pragma unroll
        for (int i = 0; i < 8; i++)
            #pragma unroll
            for (int j = 0; j < 4; j++) accS[i][j] *= scale;

        // ---- causal mask on diagonal tile (local 64x64 coords) ----
        if (kt == qt) {
            #pragma unroll
            for (int nt = 0; nt < 8; nt++) {
                int c = nt * 8 + 2 * tig;
                if (c     > rbase    ) accS[nt][0] = -1e30f;
                if (c + 1 > rbase    ) accS[nt][1] = -1e30f;
                if (c     > rbase + 8) accS[nt][2] = -1e30f;
                if (c + 1 > rbase + 8) accS[nt][3] = -1e30f;
            }
        }

        // ---- online softmax ----
        float mx0 = -1e30f, mx1 = -1e30f;
        #pragma unroll
        for (int nt = 0; nt < 8; nt++) {
            mx0 = fmaxf(mx0, fmaxf(accS[nt][0], accS[nt][1]));
            mx1 = fmaxf(mx1, fmaxf(accS[nt][2], accS[nt][3]));
        }
        mx0 = fmaxf(mx0, __shfl_xor_sync(0xffffffffu, mx0, 1));
        mx0 = fmaxf(mx0, __shfl_xor_sync(0xffffffffu, mx0, 2));
        mx1 = fmaxf(mx1, __shfl_xor_sync(0xffffffffu, mx1, 1));
        mx1 = fmaxf(mx1, __shfl_xor_sync(0xffffffffu, mx1, 2));

        float mn0 = fmaxf(m0, mx0), mn1 = fmaxf(m1, mx1);
        float al0 = __expf(m0 - mn0), al1 = __expf(m1 - mn1);
        m0 = mn0; m1 = mn1;

        float s0 = 0.0f, s1 = 0.0f;
        #pragma unroll
        for (int nt = 0; nt < 8; nt++) {
            float p0 = __expf(accS[nt][0] - mn0);
            float p1 = __expf(accS[nt][1] - mn0);
            float p2 = __expf(accS[nt][2] - mn1);
            float p3 = __expf(accS[nt][3] - mn1);
            accS[nt][0] = p0; accS[nt][1] = p1;
            accS[nt][2] = p2; accS[nt][3] = p3;
            s0 += p0 + p1; s1 += p2 + p3;
        }
        s0 += __shfl_xor_sync(0xffffffffu, s0, 1);
        s0 += __shfl_xor_sync(0xffffffffu, s0, 2);
        s1 += __shfl_xor_sync(0xffffffffu, s1, 1);
        s1 += __shfl_xor_sync(0xffffffffu, s1, 2);
        l0 = l0 * al0 + s0;
        l1 = l1 * al1 + s1;

        #pragma unroll
        for (int i = 0; i < 8; i++) {
            accO[i][0] *= al0; accO[i][1] *= al0;
            accO[i][2] *= al1; accO[i][3] *= al1;
        }

        // ---- O += P V ; P from registers (C-frag == A-frag) ----
        #pragma unroll
        for (int ki = 0; ki < 4; ki++) {
            uint32_t pa[4];
            pa[0] = f22h(accS[2 * ki][0],     accS[2 * ki][1]);
            pa[1] = f22h(accS[2 * ki][2],     accS[2 * ki][3]);
            pa[2] = f22h(accS[2 * ki + 1][0], accS[2 * ki + 1][1]);
            pa[3] = f22h(accS[2 * ki + 1][2], accS[2 * ki + 1][3]);
            #pragma unroll
            for (int dt = 0; dt < 4; dt++) {
                uint32_t vr[4];
                ldsm_x4t(vr, sV + (ki * 16 + (lane & 7) + ((lane & 8) ? 8 : 0)) * AROWB
                             + (dt * 16 + ((lane & 16) ? 8 : 0)) * 2);
                mma16816(accO[2 * dt],     pa, vr[0], vr[1]);
                mma16816(accO[2 * dt + 1], pa, vr[2], vr[3]);
            }
        }
        __syncthreads();
        buf ^= 1;
    }

    // ---- writeback ----
    float inv0 = 1.0f / l0, inv1 = 1.0f / l1;
    #pragma unroll
    for (int nt = 0; nt < 8; nt++) {
        int col = nt * 8 + 2 * tig;
        __half2 o0 = __floats2half2_rn(accO[nt][0] * inv0, accO[nt][1] * inv0);
        __half2 o1 = __floats2half2_rn(accO[nt][2] * inv1, accO[nt][3] * inv1);
        *(__half2*)(O + bout + (size_t)(qt * 64 + rbase    ) * E_DIM + col) = o0;
        *(__half2*)(O + bout + (size_t)(qt * 64 + rbase + 8) * E_DIM + col) = o1;
    }
}

// ---------------------------------------------------------------------------
// LayerNorm, warp-per-row (8 rows/CTA), shfl-only reductions.
// ---------------------------------------------------------------------------
__global__ __launch_bounds__(256)
void ln_kernel(const float* __restrict__ xin,
               const float* __restrict__ g, const float* __restrict__ beta,
               float* __restrict__ out, __half* __restrict__ outh)
{
    const int warp = threadIdx.x >> 5;
    const int lane = threadIdx.x & 31;
    const int row = blockIdx.x * 8 + warp;
    const float* xr = xin + (size_t)row * E_DIM;
    float* orow = out + (size_t)row * E_DIM;
    __half* ohrow = outh + (size_t)row * E_DIM;

    float4 xv[8];
    float lsum = 0.0f;
    #pragma unroll
    for (int j = 0; j < 8; j++) {
        xv[j] = *(const float4*)(xr + lane * 4 + j * 128);
        lsum += (xv[j].x + xv[j].y) + (xv[j].z + xv[j].w);
    }
    #pragma unroll
    for (int s = 16; s > 0; s >>= 1)
        lsum += __shfl_xor_sync(0xffffffffu, lsum, s);
    float mean = lsum * (1.0f / E_DIM);

    float lvar = 0.0f;
    #pragma unroll
    for (int j = 0; j < 8; j++) {
        float d0 = xv[j].x - mean, d1 = xv[j].y - mean;
        float d2 = xv[j].z - mean, d3 = xv[j].w - mean;
        lvar += (d0 * d0 + d1 * d1) + (d2 * d2 + d3 * d3);
    }
    #pragma unroll
    for (int s = 16; s > 0; s >>= 1)
        lvar += __shfl_xor_sync(0xffffffffu, lvar, s);
    float rstd = rsqrtf(lvar * (1.0f / E_DIM) + 1e-5f);

    #pragma unroll
    for (int j = 0; j < 8; j++) {
        int e = lane * 4 + j * 128;
        float4 gv = *(const float4*)(g + e);
        float4 bv = *(const float4*)(beta + e);
        float4 o;
        o.x = (xv[j].x - mean) * rstd * gv.x + bv.x;
        o.y = (xv[j].y - mean) * rstd * gv.y + bv.y;
        o.z = (xv[j].z - mean) * rstd * gv.z + bv.z;
        o.w = (xv[j].w - mean) * rstd * gv.w + bv.w;
        *(float4*)(orow + e) = o;
        uint2 u;
        u.x = f22h(o.x, o.y);
        u.y = f22h(o.z, o.w);
        *(uint2*)(ohrow + e) = u;
    }
}

// ---------------------------------------------------------------------------
// Launch (second stream for deferred weight transposes, fork/join via events)
// ---------------------------------------------------------------------------
extern "C" void kernel_launch(void* const* d_in, const int* in_sizes, int n_in,
                              void* d_out, int out_size)
{
    const int*   x    = (const int*)  d_in[0];
    const float* emb  = (const float*)d_in[1];
    const float* Wq   = (const float*)d_in[2];
    const float* bq   = (const float*)d_in[3];
    const float* Wk   = (const float*)d_in[4];
    const float* bk   = (const float*)d_in[5];
    const float* Wv   = (const float*)d_in[6];
    const float* bv   = (const float*)d_in[7];
    const float* Wo   = (const float*)d_in[8];
    const float* bo   = (const float*)d_in[9];
    const float* ln1g = (const float*)d_in[10];
    const float* ln1b = (const float*)d_in[11];
    const float* ln2g = (const float*)d_in[12];
    const float* ln2b = (const float*)d_in[13];
    const float* W1   = (const float*)d_in[14];
    const float* b1   = (const float*)d_in[15];
    const float* W2   = (const float*)d_in[16];
    const float* b2   = (const float*)d_in[17];
    const float* Wout = (const float*)d_in[18];
    const float* bout = (const float*)d_in[19];
    float* out = (float*)d_out;

    float *act, *tmp, *hbuf, *bqkv;
    __half *act_h, *qkv_h, *attn_h, *h_h, *ff_h, *wh;
    cudaGetSymbolAddress((void**)&act,    g_act);
    cudaGetSymbolAddress((void**)&act_h,  g_act_h);
    cudaGetSymbolAddress((void**)&qkv_h,  g_qkv_h);
    cudaGetSymbolAddress((void**)&attn_h, g_attn_h);
    cudaGetSymbolAddress((void**)&tmp,    g_tmp);
    cudaGetSymbolAddress((void**)&hbuf,   g_h);
    cudaGetSymbolAddress((void**)&h_h,    g_h_h);
    cudaGetSymbolAddress((void**)&ff_h,   g_ff_h);
    cudaGetSymbolAddress((void**)&bqkv,   g_bqkv);
    cudaGetSymbolAddress((void**)&wh,     g_wh);

    static int init_done = 0;
    static cudaStream_t s2;
    static cudaEvent_t evFork, evW12, evWout;
    if (!init_done) {
        cudaFuncSetAttribute(flash_attn_h,
                             cudaFuncAttributeMaxDynamicSharedMemorySize, ATTN_SMEM);
        cudaFuncSetAttribute(hgemm5<0, 0, 1, 0>,
                             cudaFuncAttributeMaxDynamicSharedMemorySize, GEMM_SMEM);
        cudaFuncSetAttribute(hgemm5<1, 0, 1, 0>,
                             cudaFuncAttributeMaxDynamicSharedMemorySize, GEMM_SMEM);
        cudaFuncSetAttribute(hgemm5<0, 1, 0, 1>,
                             cudaFuncAttributeMaxDynamicSharedMemorySize, GEMM_SMEM);
        cudaFuncSetAttribute(hgemm5<0, 1, 0, 0>,
                             cudaFuncAttributeMaxDynamicSharedMemorySize, GEMM_SMEM);
        cudaStreamCreateWithFlags(&s2, cudaStreamNonBlocking);
        cudaEventCreateWithFlags(&evFork, cudaEventDisableTiming);
        cudaEventCreateWithFlags(&evW12,  cudaEventDisableTiming);
        cudaEventCreateWithFlags(&evWout, cudaEventDisableTiming);
        init_done = 1;
    }

    dim3 tblk(16, 16);

    // ---- fork: deferred transposes (W1, W2, Wout) on stream s2 ----
    cudaEventRecord(evFork, 0);
    cudaStreamWaitEvent(s2, evFork, 0);
    {
        dim3 gW1(FF_DIM / 64, E_DIM / 64, L_NUM);
        transpose_half_b4<<<gW1, tblk, 0, s2>>>(W1, wh + OFF_W1, E_DIM, FF_DIM,
                                                (size_t)E_DIM * FF_DIM, W1_LSTR);
        dim3 gW2(E_DIM / 64, FF_DIM / 64, L_NUM);
        transpose_half_b4<<<gW2, tblk, 0, s2>>>(W2, wh + OFF_W2, FF_DIM, E_DIM,
                                                (size_t)FF_DIM * E_DIM, W2_LSTR);
        cudaEventRecord(evW12, s2);
        dim3 gWV(V_DIM / 64, E_DIM / 64, 1);
        transpose_half_b4<<<gWV, tblk, 0, s2>>>(Wout, wh + OFF_WOUT, E_DIM, V_DIM,
                                                (size_t)E_DIM * V_DIM, 0);
        cudaEventRecord(evWout, s2);
    }

    // ---- main stream: immediately-needed transposes + bias + embed ----
    {
        dim3 gEE(E_DIM / 64, E_DIM / 64, L_NUM);
        transpose_half_b4<<<gEE, tblk>>>(Wq, wh + 0 * WO_LSTR, E_DIM, E_DIM,
                                         (size_t)E_DIM * E_DIM, QKV_LSTR);
        transpose_half_b4<<<gEE, tblk>>>(Wk, wh + 1 * WO_LSTR, E_DIM, E_DIM,
                                         (size_t)E_DIM * E_DIM, QKV_LSTR);
        transpose_half_b4<<<gEE, tblk>>>(Wv, wh + 2 * WO_LSTR, E_DIM, E_DIM,
                                         (size_t)E_DIM * E_DIM, QKV_LSTR);
        transpose_half_b4<<<gEE, tblk>>>(Wo, wh + OFF_WO, E_DIM, E_DIM,
                                         (size_t)E_DIM * E_DIM, WO_LSTR);
        pack_qkv_bias<<<(L_NUM * QKV_STR) / 256, 256>>>(bq, bk, bv, bqkv);
    }

    embed_kernel<<<M_TOK, 256>>>(x, emb, act, act_h);

    for (int i = 0; i < L_NUM; i++) {
        size_t bo_off = (size_t)i * E_DIM;

        hgemm5<0, 0, 1, 0><<<dim3(M_TOK / GBM, QKV_STR / GBN), 256, GEMM_SMEM>>>(
            act_h, wh + (size_t)i * QKV_LSTR, bqkv + (size_t)i * QKV_STR,
            (const float*)0, (float*)0, qkv_h, QKV_STR, E_DIM);

        flash_attn_h<<<dim3(S_LEN / 64, H_DIM, N_B), 128, ATTN_SMEM>>>(qkv_h, attn_h);

        hgemm5<0, 1, 0, 1><<<dim3(M_TOK / GBM, E_DIM / GBN), 256, GEMM_SMEM>>>(
            attn_h, wh + OFF_WO + (size_t)i * WO_LSTR, bo + bo_off,
            act, tmp, (__half*)0, E_DIM, E_DIM);

        ln_kernel<<<M_TOK / 8, 256>>>(tmp, ln1g + bo_off, ln1b + bo_off, hbuf, h_h);

        if (i == 0) cudaStreamWaitEvent(0, evW12, 0);

        hgemm5<1, 0, 1, 0><<<dim3(M_TOK / GBM, FF_DIM / GBN), 256, GEMM_SMEM>>>(
            h_h, wh + OFF_W1 + (size_t)i * W1_LSTR, b1 + (size_t)i * FF_DIM,
            (const float*)0, (float*)0, ff_h, FF_DIM, E_DIM);

        hgemm5<0, 1, 0, 1><<<dim3(M_TOK / GBM, E_DIM / GBN), 256, GEMM_SMEM>>>(
            ff_h, wh + OFF_W2 + (size_t)i * W2_LSTR, b2 + bo_off,
            hbuf, tmp, (__half*)0, E_DIM, FF_DIM);

        ln_kernel<<<M_TOK / 8, 256>>>(tmp, ln2g + bo_off, ln2b + bo_off, act, act_h);
    }

    cudaStreamWaitEvent(0, evWout, 0);
    hgemm5<0, 1, 0, 0><<<dim3(M_TOK / GBM, V_DIM / GBN), 256, GEMM_SMEM>>>(
        act_h, wh + OFF_WOUT, bout, (const float*)0, out, (__half*)0, V_DIM, E_DIM);
}